// round 5
// baseline (speedup 1.0000x reference)
#include <cuda_runtime.h>
#include <cstddef>

#define IMG_H 128
#define IMG_W 128

// Integer code cutoffs per threshold: out[...,t] = (code >= g_ct[t])
__device__ __align__(16) int g_ct[8];

// ---------------------------------------------------------------------------
// Prologue: replicate GLTEstimator threshold math with XLA's exact fp32
// rounding order, then convert each float threshold into an integer LBP-code
// cutoff (code in 0..255, x(code) = code*fl(1/127.5) - 1, mul-then-sub, no fma).
// ---------------------------------------------------------------------------
__global__ void glt_cutoffs_kernel(const float* __restrict__ lt) {
    float p[8];
#pragma unroll
    for (int i = 0; i < 8; i++)
        p[i] = __fadd_rn(fmaxf(lt[i], 0.0f), 1e-5f);   // relu(x) + 1e-5

    // sequential sum (XLA CPU reduce order)
    float S = p[0];
#pragma unroll
    for (int i = 1; i < 8; i++) S = __fadd_rn(S, p[i]);

    float n[8];
#pragma unroll
    for (int i = 0; i < 8; i++) n[i] = __fdiv_rn(p[i], S);

    // jnp.cumsum -> lax.associative_scan tree order for n=8
    float b0 = __fadd_rn(n[0], n[1]);
    float b1 = __fadd_rn(n[2], n[3]);
    float b2 = __fadd_rn(n[4], n[5]);
    float b3 = __fadd_rn(n[6], n[7]);
    float c0 = __fadd_rn(b0, b1);
    float c1 = __fadd_rn(b2, b3);
    float r[8];
    r[0] = n[0];
    r[1] = b0;
    r[2] = __fadd_rn(b0, n[2]);
    r[3] = c0;
    r[4] = __fadd_rn(c0, n[4]);
    r[5] = __fadd_rn(c0, b2);
    r[6] = __fadd_rn(__fadd_rn(c0, b2), n[6]);
    r[7] = __fadd_rn(c0, c1);

    const float C = (float)(1.0 / 127.5);  // == np.float32(1.0/127.5)
#pragma unroll 1
    for (int t = 0; t < 8; t++) {
        float thr = __fsub_rn(__fmul_rn(r[t], 2.0f), 1.0f);  // cumsum*2 - 1
        int ct = 256;  // "never" sentinel
        for (int k = 0; k < 256; k++) {
            // x(k) exactly as XLA: mul then sub, round-to-nearest, NO fma
            float x = __fsub_rn(__fmul_rn((float)k, C), 1.0f);
            if (x >= thr) { ct = k; break; }
        }
        g_ct[t] = ct;
    }
}

// ---------------------------------------------------------------------------
// Main: census-LBP code per pixel + 8 integer threshold compares.
// Block (32,8), one pixel per thread, 32B output per thread (2x STG.128).
// ---------------------------------------------------------------------------
__global__ __launch_bounds__(256) void lbp_glt_kernel(
    const float* __restrict__ img, float* __restrict__ out) {
    const int x = blockIdx.x * 32 + threadIdx.x;
    const int y = blockIdx.y * 8 + threadIdx.y;
    const int b = blockIdx.z;

    const float* base = img + (size_t)b * (IMG_H * IMG_W);
    const float c = base[y * IMG_W + x];

    float n0, n1, n2, n3, n4, n5, n6, n7;
    if (x > 0 && x < IMG_W - 1 && y > 0 && y < IMG_H - 1) {
        // interior fast path: unchecked loads
        const float* rm = base + (y - 1) * IMG_W + x;
        const float* rc = base + (y    ) * IMG_W + x;
        const float* rp = base + (y + 1) * IMG_W + x;
        n0 = rm[-1]; n1 = rm[0]; n2 = rm[1];
        n7 = rc[-1];             n3 = rc[1];
        n6 = rp[-1]; n5 = rp[0]; n4 = rp[1];
    } else {
        // zero-padded border (matches jnp.pad with zeros)
        auto ld = [&](int yy, int xx) -> float {
            return (yy >= 0 && yy < IMG_H && xx >= 0 && xx < IMG_W)
                       ? base[yy * IMG_W + xx] : 0.0f;
        };
        n0 = ld(y - 1, x - 1); n1 = ld(y - 1, x); n2 = ld(y - 1, x + 1);
        n3 = ld(y, x + 1);     n4 = ld(y + 1, x + 1); n5 = ld(y + 1, x);
        n6 = ld(y + 1, x - 1); n7 = ld(y, x - 1);
    }

    // census code, neighbor order matches _NEIGHBORS; ties (>=) give 1
    int code = (n0 >= c)
             | ((n1 >= c) << 1)
             | ((n2 >= c) << 2)
             | ((n3 >= c) << 3)
             | ((n4 >= c) << 4)
             | ((n5 >= c) << 5)
             | ((n6 >= c) << 6)
             | ((n7 >= c) << 7);

    const int4 ct0 = *reinterpret_cast<const int4*>(&g_ct[0]);
    const int4 ct1 = *reinterpret_cast<const int4*>(&g_ct[4]);

    float4 o0, o1;
    o0.x = (code >= ct0.x) ? 1.0f : 0.0f;
    o0.y = (code >= ct0.y) ? 1.0f : 0.0f;
    o0.z = (code >= ct0.z) ? 1.0f : 0.0f;
    o0.w = (code >= ct0.w) ? 1.0f : 0.0f;
    o1.x = (code >= ct1.x) ? 1.0f : 0.0f;
    o1.y = (code >= ct1.y) ? 1.0f : 0.0f;
    o1.z = (code >= ct1.z) ? 1.0f : 0.0f;
    o1.w = (code >= ct1.w) ? 1.0f : 0.0f;

    float4* op = reinterpret_cast<float4*>(
        out + (((size_t)b * IMG_H + y) * IMG_W + x) * 8);
    op[0] = o0;
    op[1] = o1;
}

extern "C" void kernel_launch(void* const* d_in, const int* in_sizes, int n_in,
                              void* d_out, int out_size) {
    const float* images = (const float*)d_in[0];
    const float* latent = (const float*)d_in[1];
    float* out = (float*)d_out;

    const int B = in_sizes[0] / (IMG_H * IMG_W);

    glt_cutoffs_kernel<<<1, 1>>>(latent);

    dim3 block(32, 8, 1);
    dim3 grid(IMG_W / 32, IMG_H / 8, B);
    lbp_glt_kernel<<<grid, block>>>(images, out);
}

// round 6
// speedup vs baseline: 1.3341x; 1.3341x over previous
#include <cuda_runtime.h>
#include <cstddef>

#define IMG_H 128
#define IMG_W 128

// Integer code cutoffs per threshold: out[...,t] = (code >= g_ct[t])
__device__ __align__(16) int g_ct[8];

// ---------------------------------------------------------------------------
// Prologue (parallel): thread k evaluates x(k) with XLA's exact fp32 rounding,
// compares against all 8 thresholds, and the per-warp minimum k satisfying
// x(k) >= thr[t] is atomically min-reduced into s_ct[t]. x(k) is monotone
// nondecreasing in k, so min-k is exactly the cutoff.
// ---------------------------------------------------------------------------
__global__ void glt_cutoffs_kernel(const float* __restrict__ lt) {
    __shared__ int s_ct[8];
    const int tid = threadIdx.x;          // 0..255 == candidate code k
    if (tid < 8) s_ct[tid] = 256;         // "never" sentinel
    __syncthreads();

    // Threshold math, identical rounding order to the passing R4 kernel
    float p[8];
#pragma unroll
    for (int i = 0; i < 8; i++)
        p[i] = __fadd_rn(fmaxf(lt[i], 0.0f), 1e-5f);   // relu + 1e-5

    float S = p[0];
#pragma unroll
    for (int i = 1; i < 8; i++) S = __fadd_rn(S, p[i]); // sequential sum

    float n[8];
#pragma unroll
    for (int i = 0; i < 8; i++) n[i] = __fdiv_rn(p[i], S);

    // cumsum via associative_scan tree order (n=8)
    float b0 = __fadd_rn(n[0], n[1]);
    float b1 = __fadd_rn(n[2], n[3]);
    float b2 = __fadd_rn(n[4], n[5]);
    float b3 = __fadd_rn(n[6], n[7]);
    float c0 = __fadd_rn(b0, b1);
    float c1 = __fadd_rn(b2, b3);
    float r[8];
    r[0] = n[0];
    r[1] = b0;
    r[2] = __fadd_rn(b0, n[2]);
    r[3] = c0;
    r[4] = __fadd_rn(c0, n[4]);
    r[5] = __fadd_rn(c0, b2);
    r[6] = __fadd_rn(__fadd_rn(c0, b2), n[6]);
    r[7] = __fadd_rn(c0, c1);

    const float C = (float)(1.0 / 127.5);
    const float x = __fsub_rn(__fmul_rn((float)tid, C), 1.0f); // x(k), no fma

    const int lane = tid & 31;
#pragma unroll
    for (int t = 0; t < 8; t++) {
        const float thr = __fsub_rn(__fmul_rn(r[t], 2.0f), 1.0f);
        unsigned m = __ballot_sync(0xffffffffu, x >= thr);
        if (m && lane == (__ffs(m) - 1))
            atomicMin(&s_ct[t], tid);     // smallest satisfying k in this warp
    }
    __syncthreads();
    if (tid < 8) g_ct[tid] = s_ct[tid];
}

// ---------------------------------------------------------------------------
// Main: 4 pixels per thread along y (rolling 3-row window). Stores stay
// warp-contiguous (lane-consecutive pixels per store), loads amortized to
// 4.5/pixel, census + threshold bookkeeping amortized 4x.
// Block (32,8) covers a 32x32 tile; grid (4,4,B).
// ---------------------------------------------------------------------------
__global__ __launch_bounds__(256) void lbp_glt_kernel(
    const float* __restrict__ img, float* __restrict__ out) {
    const int x  = blockIdx.x * 32 + threadIdx.x;
    const int y0 = blockIdx.y * 32 + threadIdx.y * 4;   // first of 4 rows
    const int b  = blockIdx.z;

    const float* base = img + (size_t)b * (IMG_H * IMG_W);
    const bool xm_ok = (x > 0);
    const bool xp_ok = (x < IMG_W - 1);

    // load one padded row triple (x-1, x, x+1) at row yy (zero-pad OOB)
    auto ldrow = [&](int yy, float& l, float& c, float& r) {
        if (yy >= 0 && yy < IMG_H) {
            const float* row = base + yy * IMG_W + x;
            c = row[0];
            l = xm_ok ? row[-1] : 0.0f;
            r = xp_ok ? row[1]  : 0.0f;
        } else {
            l = 0.0f; c = 0.0f; r = 0.0f;
        }
    };

    float t0, t1, t2, m0, m1, m2, bb0, bb1, bb2;
    ldrow(y0 - 1, t0, t1, t2);
    ldrow(y0,     m0, m1, m2);

    const int4 ct0 = *reinterpret_cast<const int4*>(&g_ct[0]);
    const int4 ct1 = *reinterpret_cast<const int4*>(&g_ct[4]);

    float* op = out + (((size_t)b * IMG_H + y0) * IMG_W + x) * 8;

#pragma unroll
    for (int i = 0; i < 4; i++) {
        ldrow(y0 + 1 + i, bb0, bb1, bb2);

        const float c = m1;
        // census code, _NEIGHBORS order, ties (>=) -> 1
        int code = (t0  >= c)
                 | ((t1  >= c) << 1)
                 | ((t2  >= c) << 2)
                 | ((m2  >= c) << 3)
                 | ((bb2 >= c) << 4)
                 | ((bb1 >= c) << 5)
                 | ((bb0 >= c) << 6)
                 | ((m0  >= c) << 7);

        float4 o0, o1;
        o0.x = (code >= ct0.x) ? 1.0f : 0.0f;
        o0.y = (code >= ct0.y) ? 1.0f : 0.0f;
        o0.z = (code >= ct0.z) ? 1.0f : 0.0f;
        o0.w = (code >= ct0.w) ? 1.0f : 0.0f;
        o1.x = (code >= ct1.x) ? 1.0f : 0.0f;
        o1.y = (code >= ct1.y) ? 1.0f : 0.0f;
        o1.z = (code >= ct1.z) ? 1.0f : 0.0f;
        o1.w = (code >= ct1.w) ? 1.0f : 0.0f;

        float4* p4 = reinterpret_cast<float4*>(op + (size_t)i * IMG_W * 8);
        __stcs(p4,     o0);   // streaming: write-once output, skip L2 dwell
        __stcs(p4 + 1, o1);

        // roll the window down one row
        t0 = m0;  t1 = m1;  t2 = m2;
        m0 = bb0; m1 = bb1; m2 = bb2;
    }
}

extern "C" void kernel_launch(void* const* d_in, const int* in_sizes, int n_in,
                              void* d_out, int out_size) {
    const float* images = (const float*)d_in[0];
    const float* latent = (const float*)d_in[1];
    float* out = (float*)d_out;

    const int B = in_sizes[0] / (IMG_H * IMG_W);

    glt_cutoffs_kernel<<<1, 256>>>(latent);

    dim3 block(32, 8, 1);
    dim3 grid(IMG_W / 32, IMG_H / 32, B);
    lbp_glt_kernel<<<grid, block>>>(images, out);
}